// round 14
// baseline (speedup 1.0000x reference)
#include <cuda_runtime.h>
#include <cuda_bf16.h>

#define NUM_REL   20000
#define NUM_EDGES 640000
#define DIM       128
#define NUM_HEAD  8
#define DIM_HID   16
#define NUM_BIN   10
#define NEG       0.2f
#define SCAN_B    79    // ceil(20000/256)

#define PACK2(u, lo, hi)  asm("mov.b64 %0, {%1, %2};" : "=l"(u) : "f"(lo), "f"(hi))
#define UNPACK2(lo, hi, u) asm("mov.b64 {%0, %1}, %2;" : "=f"(lo), "=f"(hi) : "l"(u))
#define FMA2(d, a, b, c)  asm("fma.rn.f32x2 %0, %1, %2, %3;" : "=l"(d) : "l"(a), "l"(b), "l"(c))

// ---------------- device scratch (static: no allocs allowed) ----------------
__device__ float g_P1[NUM_REL * DIM];
__device__ float g_P2[NUM_REL * DIM];
__device__ float g_M [NUM_REL * DIM];
__device__ int   g_cnt[NUM_REL];
__device__ int   g_off[NUM_REL + 1];
__device__ int   g_cur[NUM_REL];
__device__ int   g_sorted[NUM_EDGES];   // packed: tail | (bin << 20)
__device__ int   g_bsum[SCAN_B + 1];

__global__ void K_zero() {
    int i = blockIdx.x * blockDim.x + threadIdx.x;
    if (i < NUM_REL) g_cnt[i] = 0;
}

__global__ void K_hist(const int* __restrict__ trip) {
    int e = blockIdx.x * blockDim.x + threadIdx.x;
    if (e < NUM_EDGES) atomicAdd(&g_cnt[trip[e * 3]], 1);
}

// ---------------- 3-phase parallel scan ----------------
__global__ void K_scan1() {
    __shared__ int sh[256];
    int tid = threadIdx.x;
    int i = blockIdx.x * 256 + tid;
    int v = (i < NUM_REL) ? g_cnt[i] : 0;
    sh[tid] = v;
    __syncthreads();
#pragma unroll
    for (int off = 1; off < 256; off <<= 1) {
        int t = (tid >= off) ? sh[tid - off] : 0;
        __syncthreads();
        sh[tid] += t;
        __syncthreads();
    }
    if (i < NUM_REL) g_off[i] = sh[tid] - v;
    if (tid == 255) g_bsum[blockIdx.x] = sh[255];
}

__global__ void K_scan2() {
    __shared__ int sh[128];
    int tid = threadIdx.x;
    int v = (tid < SCAN_B) ? g_bsum[tid] : 0;
    sh[tid] = v;
    __syncthreads();
#pragma unroll
    for (int off = 1; off < 128; off <<= 1) {
        int t = (tid >= off) ? sh[tid - off] : 0;
        __syncthreads();
        sh[tid] += t;
        __syncthreads();
    }
    if (tid < SCAN_B) g_bsum[tid] = sh[tid] - v;
    if (tid == 127) g_off[NUM_REL] = sh[127];
}

__global__ void K_scan3() {
    int i = blockIdx.x * 256 + threadIdx.x;
    if (i < NUM_REL) {
        int o = g_off[i] + g_bsum[blockIdx.x];
        g_off[i] = o;
        g_cur[i] = o;
    }
}

__global__ void K_scatter(const int* __restrict__ trip) {
    int e = blockIdx.x * blockDim.x + threadIdx.x;
    if (e < NUM_EDGES) {
        int h    = trip[e * 3];
        int tail = trip[e * 3 + 1];
        int bin  = trip[e * 3 + 2];
        int pos = atomicAdd(&g_cur[h], 1);
        g_sorted[pos] = tail | (bin << 20);
    }
}

// ------- 20000x128x128 SGEMM, FFMA2 + transposed emb tile -------
// Weight transpose folded into the WtS fill (K_pre eliminated): source rows are
// k-contiguous, so the fill LDG.128 is coalesced; transposed STS.32 has <=4-way conflicts.
#define ET_STRIDE 36
__global__ void __launch_bounds__(256) K_gemm(const float* __restrict__ emb,
                                              const float* __restrict__ attn_w,
                                              const float* __restrict__ aggr_w,
                                              const float* __restrict__ apb,
                                              const float* __restrict__ agb) {
    int which = blockIdx.y;
    const float* __restrict__ src = (which == 2) ? aggr_w : attn_w;
    int stride = (which == 2) ? 128 : 256;
    int off    = (which == 1) ? 128 : 0;
    float*       __restrict__ op = (which == 0) ? g_P1 : (which == 1) ? g_P2 : g_M;
    const float* bias = (which == 0) ? apb : (which == 1) ? (const float*)0 : agb;

    __shared__ float eT[128 * ET_STRIDE];
    __shared__ float WtS[32 * 132];        // [k_local][j], row pad 132

    int tid = threadIdx.x;
    int rbase = blockIdx.x * 32;

    for (int idx = tid; idx < 32 * 128; idx += 256) {
        int rr = idx >> 7;
        int kk = idx & 127;
        eT[kk * ET_STRIDE + rr] = emb[(size_t)(rbase + rr) * DIM + kk];
    }

    int jt = tid & 31, j0 = jt * 4;
    int rt = tid >> 5, r0 = rt * 4;

    unsigned long long acc01[4], acc23[4];
#pragma unroll
    for (int a = 0; a < 4; a++) { acc01[a] = 0ull; acc23[a] = 0ull; }

    for (int kc = 0; kc < 4; kc++) {
        __syncthreads();
        // transposed fill: WtS[k_local][j] = src[j*stride + off + kc*32 + k_local]
#pragma unroll
        for (int i = 0; i < 4; i++) {
            int u = tid + i * 256;          // [0,1024)
            int j = u >> 3, k4 = u & 7;     // j: 0..127, k4: 0..7 (4 k's each)
            float4 wv = *(const float4*)(src + (size_t)j * stride + off + kc * 32 + k4 * 4);
            WtS[(k4 * 4 + 0) * 132 + j] = wv.x;
            WtS[(k4 * 4 + 1) * 132 + j] = wv.y;
            WtS[(k4 * 4 + 2) * 132 + j] = wv.z;
            WtS[(k4 * 4 + 3) * 132 + j] = wv.w;
        }
        __syncthreads();
#pragma unroll
        for (int kk = 0; kk < 32; kk++) {
            int k = kc * 32 + kk;
            float4 wv = *(float4*)&WtS[kk * 132 + j0];
            float4 ev = *(float4*)&eT[k * ET_STRIDE + r0];
            unsigned long long w01, w23;
            PACK2(w01, wv.x, wv.y);
            PACK2(w23, wv.z, wv.w);
            unsigned long long ee;
            PACK2(ee, ev.x, ev.x);
            FMA2(acc01[0], ee, w01, acc01[0]);
            FMA2(acc23[0], ee, w23, acc23[0]);
            PACK2(ee, ev.y, ev.y);
            FMA2(acc01[1], ee, w01, acc01[1]);
            FMA2(acc23[1], ee, w23, acc23[1]);
            PACK2(ee, ev.z, ev.z);
            FMA2(acc01[2], ee, w01, acc01[2]);
            FMA2(acc23[2], ee, w23, acc23[2]);
            PACK2(ee, ev.w, ev.w);
            FMA2(acc01[3], ee, w01, acc01[3]);
            FMA2(acc23[3], ee, w23, acc23[3]);
        }
    }

    float4 bv = make_float4(0.f, 0.f, 0.f, 0.f);
    if (bias) bv = *(const float4*)(bias + j0);
#pragma unroll
    for (int a = 0; a < 4; a++) {
        float4 o;
        UNPACK2(o.x, o.y, acc01[a]);
        UNPACK2(o.z, o.w, acc23[a]);
        o.x += bv.x; o.y += bv.y; o.z += bv.z; o.w += bv.w;
        *(float4*)&op[(size_t)(rbase + r0 + a) * DIM + j0] = o;
    }
}

// ------- warp-per-relation: single-pass online softmax aggregation (R12 verbatim) -------
__global__ void __launch_bounds__(256) K_main(const float* __restrict__ attn_bin,
                                              const float* __restrict__ attn_vec,
                                              float* __restrict__ out) {
    __shared__ float binS[NUM_BIN * NUM_HEAD];

    int tid = threadIdx.x;
    int w = tid >> 5, lane = tid & 31, h = lane >> 2;

    if (tid < NUM_BIN * NUM_HEAD) {
        float b = attn_bin[tid];
        binS[tid] = (b >= 0.f) ? b : NEG * b;
    }
    __syncthreads();

    int r = blockIdx.x * 8 + w;          // 2500 blocks x 8 warps
    int start = g_off[r];
    int cnt = g_off[r + 1] - start;

    if (cnt == 0) {
        *(float4*)(out + (size_t)r * 128 + lane * 4) = make_float4(0.f, 0.f, 0.f, 0.f);
        return;
    }

    float4 p1 = *(const float4*)(g_P1 + (size_t)r * 128 + lane * 4);
    float4 v  = *(const float4*)(attn_vec + lane * 4);

    float m = -3.0e38f, s = 0.f;
    float4 acc = make_float4(0.f, 0.f, 0.f, 0.f);

    for (int base = 0; base < cnt; base += 32) {
        int rem = cnt - base;
        int n = (rem < 32) ? rem : 32;
        int myval = (lane < rem) ? g_sorted[start + base + lane] : 0;
#pragma unroll 4
        for (int i = 0; i < n; i++) {
            int val  = __shfl_sync(0xffffffffu, myval, i);
            int tail = val & 0xFFFFF;
            int bin  = val >> 20;
            float4 p2 = *(const float4*)(g_P2 + (size_t)tail * 128 + lane * 4);
            float4 mv = *(const float4*)(g_M  + (size_t)tail * 128 + lane * 4);
            float x0 = p1.x + p2.x; x0 = (x0 >= 0.f) ? x0 : NEG * x0;
            float x1 = p1.y + p2.y; x1 = (x1 >= 0.f) ? x1 : NEG * x1;
            float x2 = p1.z + p2.z; x2 = (x2 >= 0.f) ? x2 : NEG * x2;
            float x3 = p1.w + p2.w; x3 = (x3 >= 0.f) ? x3 : NEG * x3;
            float part = x0 * v.x + x1 * v.y + x2 * v.z + x3 * v.w;
            part += __shfl_xor_sync(0xffffffffu, part, 1);
            part += __shfl_xor_sync(0xffffffffu, part, 2);
            float score = part + binS[bin * 8 + h];
            if (score > m) {
                float c = __expf(m - score);
                s *= c;
                acc.x *= c; acc.y *= c; acc.z *= c; acc.w *= c;
                m = score;
            }
            float wt = __expf(score - m);
            s += wt;
            acc.x = fmaf(wt, mv.x, acc.x);
            acc.y = fmaf(wt, mv.y, acc.y);
            acc.z = fmaf(wt, mv.z, acc.z);
            acc.w = fmaf(wt, mv.w, acc.w);
        }
    }

    float inv = 1.f / (s + 1e-16f);
    float4 o;
    o.x = acc.x * inv; o.y = acc.y * inv; o.z = acc.z * inv; o.w = acc.w * inv;
    *(float4*)(out + (size_t)r * 128 + lane * 4) = o;
}

// ---------------- launch: sort chain forked onto a second stream ----------------
static cudaStream_t g_s2 = 0;
static cudaEvent_t  g_evFork = 0, g_evJoin = 0;

extern "C" void kernel_launch(void* const* d_in, const int* in_sizes, int n_in,
                              void* d_out, int out_size) {
    const float* emb  = (const float*)d_in[0];
    const int*   trip = (const int*)d_in[1];
    const float* apw  = (const float*)d_in[2];
    const float* apb  = (const float*)d_in[3];
    const float* abin = (const float*)d_in[4];
    const float* avec = (const float*)d_in[5];
    const float* agw  = (const float*)d_in[6];
    const float* agb  = (const float*)d_in[7];
    float* out = (float*)d_out;

    if (g_s2 == 0) {
        cudaStreamCreateWithFlags(&g_s2, cudaStreamNonBlocking);
        cudaEventCreateWithFlags(&g_evFork, cudaEventDisableTiming);
        cudaEventCreateWithFlags(&g_evJoin, cudaEventDisableTiming);
    }

    cudaEventRecord(g_evFork, 0);
    cudaStreamWaitEvent(g_s2, g_evFork, 0);

    K_zero   <<<(NUM_REL   + 255) / 256, 256, 0, g_s2>>>();
    K_hist   <<<(NUM_EDGES + 255) / 256, 256, 0, g_s2>>>(trip);
    K_scan1  <<<SCAN_B, 256, 0, g_s2>>>();
    K_scan2  <<<1, 128, 0, g_s2>>>();
    K_scan3  <<<SCAN_B, 256, 0, g_s2>>>();
    K_scatter<<<(NUM_EDGES + 255) / 256, 256, 0, g_s2>>>(trip);
    cudaEventRecord(g_evJoin, g_s2);

    K_gemm<<<dim3(NUM_REL / 32, 3), 256>>>(emb, apw, agw, apb, agb);

    cudaStreamWaitEvent(0, g_evJoin, 0);
    K_main<<<NUM_REL / 8, 256>>>(abin, avec, out);
}

// round 15
// speedup vs baseline: 1.0936x; 1.0936x over previous
#include <cuda_runtime.h>
#include <cuda_bf16.h>

#define NUM_REL   20000
#define NUM_EDGES 640000
#define DIM       128
#define NUM_HEAD  8
#define DIM_HID   16
#define NUM_BIN   10
#define NEG       0.2f
#define SCAN_B    79    // ceil(20000/256)

#define PACK2(u, lo, hi)  asm("mov.b64 %0, {%1, %2};" : "=l"(u) : "f"(lo), "f"(hi))
#define UNPACK2(lo, hi, u) asm("mov.b64 {%0, %1}, %2;" : "=f"(lo), "=f"(hi) : "l"(u))
#define FMA2(d, a, b, c)  asm("fma.rn.f32x2 %0, %1, %2, %3;" : "=l"(d) : "l"(a), "l"(b), "l"(c))

// ---------------- device scratch (static: no allocs allowed) ----------------
__device__ float g_P1[NUM_REL * DIM];
__device__ float g_PM[NUM_REL * 256];   // interleaved: [rel][0:128)=P2 row, [128:256)=M row
__device__ float g_Wt1[DIM * DIM];
__device__ float g_Wt2[DIM * DIM];
__device__ float g_Wt3[DIM * DIM];
__device__ int   g_cnt[NUM_REL];
__device__ int   g_off[NUM_REL + 1];
__device__ int   g_cur[NUM_REL];
__device__ int   g_sorted[NUM_EDGES];   // packed: tail | (bin << 20)
__device__ int   g_bsum[SCAN_B + 1];

// ---------------- weight transpose (R12 verbatim) ----------------
__global__ void K_pre(const float* __restrict__ attn_w, const float* __restrict__ aggr_w) {
    int id = blockIdx.x * blockDim.x + threadIdx.x;
    if (id >= 3 * DIM * DIM) return;
    int mtx = id / (DIM * DIM);
    int rem = id % (DIM * DIM);
    int j = rem / DIM, k = rem % DIM;
    if (mtx == 0)       g_Wt1[k * DIM + j] = attn_w[j * (2 * DIM) + k];
    else if (mtx == 1)  g_Wt2[k * DIM + j] = attn_w[j * (2 * DIM) + DIM + k];
    else                g_Wt3[k * DIM + j] = aggr_w[j * DIM + k];
}

__global__ void K_zero() {
    int i = blockIdx.x * blockDim.x + threadIdx.x;
    if (i < NUM_REL) g_cnt[i] = 0;
}

__global__ void K_hist(const int* __restrict__ trip) {
    int e = blockIdx.x * blockDim.x + threadIdx.x;
    if (e < NUM_EDGES) atomicAdd(&g_cnt[trip[e * 3]], 1);
}

// ---------------- 3-phase parallel scan (R12 verbatim) ----------------
__global__ void K_scan1() {
    __shared__ int sh[256];
    int tid = threadIdx.x;
    int i = blockIdx.x * 256 + tid;
    int v = (i < NUM_REL) ? g_cnt[i] : 0;
    sh[tid] = v;
    __syncthreads();
#pragma unroll
    for (int off = 1; off < 256; off <<= 1) {
        int t = (tid >= off) ? sh[tid - off] : 0;
        __syncthreads();
        sh[tid] += t;
        __syncthreads();
    }
    if (i < NUM_REL) g_off[i] = sh[tid] - v;
    if (tid == 255) g_bsum[blockIdx.x] = sh[255];
}

__global__ void K_scan2() {
    __shared__ int sh[128];
    int tid = threadIdx.x;
    int v = (tid < SCAN_B) ? g_bsum[tid] : 0;
    sh[tid] = v;
    __syncthreads();
#pragma unroll
    for (int off = 1; off < 128; off <<= 1) {
        int t = (tid >= off) ? sh[tid - off] : 0;
        __syncthreads();
        sh[tid] += t;
        __syncthreads();
    }
    if (tid < SCAN_B) g_bsum[tid] = sh[tid] - v;
    if (tid == 127) g_off[NUM_REL] = sh[127];
}

__global__ void K_scan3() {
    int i = blockIdx.x * 256 + threadIdx.x;
    if (i < NUM_REL) {
        int o = g_off[i] + g_bsum[blockIdx.x];
        g_off[i] = o;
        g_cur[i] = o;
    }
}

__global__ void K_scatter(const int* __restrict__ trip) {
    int e = blockIdx.x * blockDim.x + threadIdx.x;
    if (e < NUM_EDGES) {
        int h    = trip[e * 3];
        int tail = trip[e * 3 + 1];
        int bin  = trip[e * 3 + 2];
        int pos = atomicAdd(&g_cur[h], 1);
        g_sorted[pos] = tail | (bin << 20);
    }
}

// ------- 20000x128x128 SGEMM (R12 body; only output stride/offset parametrized) -------
#define ET_STRIDE 36
__global__ void __launch_bounds__(256) K_gemm(const float* __restrict__ emb,
                                              const float* __restrict__ apb,
                                              const float* __restrict__ agb) {
    int which = blockIdx.y;
    const float* __restrict__ Wt = (which == 0) ? g_Wt1 : (which == 1) ? g_Wt2 : g_Wt3;
    float*       __restrict__ op = (which == 0) ? g_P1  : g_PM;
    int ostride = (which == 0) ? 128 : 256;
    int ooff    = (which == 2) ? 128 : 0;     // M rows land in second half of g_PM
    const float* bias = (which == 0) ? apb : (which == 1) ? (const float*)0 : agb;

    __shared__ float eT[128 * ET_STRIDE];
    __shared__ float WtS[32 * 132];

    int tid = threadIdx.x;
    int rbase = blockIdx.x * 32;

    for (int idx = tid; idx < 32 * 128; idx += 256) {
        int rr = idx >> 7;
        int kk = idx & 127;
        eT[kk * ET_STRIDE + rr] = emb[(size_t)(rbase + rr) * DIM + kk];
    }

    int jt = tid & 31, j0 = jt * 4;
    int rt = tid >> 5, r0 = rt * 4;

    unsigned long long acc01[4], acc23[4];
#pragma unroll
    for (int a = 0; a < 4; a++) { acc01[a] = 0ull; acc23[a] = 0ull; }

    for (int kc = 0; kc < 4; kc++) {
        __syncthreads();
#pragma unroll
        for (int i = 0; i < 4; i++) {
            int v = tid + i * 256;
            int kl = v >> 5, jq = v & 31;
            *(float4*)&WtS[kl * 132 + jq * 4] = ((const float4*)Wt)[kc * 1024 + v];
        }
        __syncthreads();
#pragma unroll
        for (int kk = 0; kk < 32; kk++) {
            int k = kc * 32 + kk;
            float4 wv = *(float4*)&WtS[kk * 132 + j0];
            float4 ev = *(float4*)&eT[k * ET_STRIDE + r0];
            unsigned long long w01, w23;
            PACK2(w01, wv.x, wv.y);
            PACK2(w23, wv.z, wv.w);
            unsigned long long ee;
            PACK2(ee, ev.x, ev.x);
            FMA2(acc01[0], ee, w01, acc01[0]);
            FMA2(acc23[0], ee, w23, acc23[0]);
            PACK2(ee, ev.y, ev.y);
            FMA2(acc01[1], ee, w01, acc01[1]);
            FMA2(acc23[1], ee, w23, acc23[1]);
            PACK2(ee, ev.z, ev.z);
            FMA2(acc01[2], ee, w01, acc01[2]);
            FMA2(acc23[2], ee, w23, acc23[2]);
            PACK2(ee, ev.w, ev.w);
            FMA2(acc01[3], ee, w01, acc01[3]);
            FMA2(acc23[3], ee, w23, acc23[3]);
        }
    }

    float4 bv = make_float4(0.f, 0.f, 0.f, 0.f);
    if (bias) bv = *(const float4*)(bias + j0);
#pragma unroll
    for (int a = 0; a < 4; a++) {
        float4 o;
        UNPACK2(o.x, o.y, acc01[a]);
        UNPACK2(o.z, o.w, acc23[a]);
        o.x += bv.x; o.y += bv.y; o.z += bv.z; o.w += bv.w;
        *(float4*)&op[(size_t)(rbase + r0 + a) * ostride + ooff + j0] = o;
    }
}

// ------- warp-per-relation single-pass (R12 verbatim, shared-base gathers) -------
__global__ void __launch_bounds__(256) K_main(const float* __restrict__ attn_bin,
                                              const float* __restrict__ attn_vec,
                                              float* __restrict__ out) {
    __shared__ float binS[NUM_BIN * NUM_HEAD];

    int tid = threadIdx.x;
    int w = tid >> 5, lane = tid & 31, h = lane >> 2;

    if (tid < NUM_BIN * NUM_HEAD) {
        float b = attn_bin[tid];
        binS[tid] = (b >= 0.f) ? b : NEG * b;
    }
    __syncthreads();

    int r = blockIdx.x * 8 + w;          // 2500 blocks x 8 warps
    int start = g_off[r];
    int cnt = g_off[r + 1] - start;

    if (cnt == 0) {
        *(float4*)(out + (size_t)r * 128 + lane * 4) = make_float4(0.f, 0.f, 0.f, 0.f);
        return;
    }

    float4 p1 = *(const float4*)(g_P1 + (size_t)r * 128 + lane * 4);
    float4 v  = *(const float4*)(attn_vec + lane * 4);

    float m = -3.0e38f, s = 0.f;
    float4 acc = make_float4(0.f, 0.f, 0.f, 0.f);

    for (int base = 0; base < cnt; base += 32) {
        int rem = cnt - base;
        int n = (rem < 32) ? rem : 32;
        int myval = (lane < rem) ? g_sorted[start + base + lane] : 0;
#pragma unroll 4
        for (int i = 0; i < n; i++) {
            int val  = __shfl_sync(0xffffffffu, myval, i);
            int tail = val & 0xFFFFF;
            int bin  = val >> 20;
            const float* pm = g_PM + (size_t)tail * 256 + lane * 4;   // one base for both rows
            float4 p2 = *(const float4*)pm;
            float4 mv = *(const float4*)(pm + 128);
            float x0 = p1.x + p2.x; x0 = (x0 >= 0.f) ? x0 : NEG * x0;
            float x1 = p1.y + p2.y; x1 = (x1 >= 0.f) ? x1 : NEG * x1;
            float x2 = p1.z + p2.z; x2 = (x2 >= 0.f) ? x2 : NEG * x2;
            float x3 = p1.w + p2.w; x3 = (x3 >= 0.f) ? x3 : NEG * x3;
            float part = x0 * v.x + x1 * v.y + x2 * v.z + x3 * v.w;
            part += __shfl_xor_sync(0xffffffffu, part, 1);
            part += __shfl_xor_sync(0xffffffffu, part, 2);
            float score = part + binS[bin * 8 + h];
            if (score > m) {
                float c = __expf(m - score);
                s *= c;
                acc.x *= c; acc.y *= c; acc.z *= c; acc.w *= c;
                m = score;
            }
            float wt = __expf(score - m);
            s += wt;
            acc.x = fmaf(wt, mv.x, acc.x);
            acc.y = fmaf(wt, mv.y, acc.y);
            acc.z = fmaf(wt, mv.z, acc.z);
            acc.w = fmaf(wt, mv.w, acc.w);
        }
    }

    float inv = 1.f / (s + 1e-16f);
    float4 o;
    o.x = acc.x * inv; o.y = acc.y * inv; o.z = acc.z * inv; o.w = acc.w * inv;
    *(float4*)(out + (size_t)r * 128 + lane * 4) = o;
}

// ---------------- launch: sort chain forked onto a second stream (R12 verbatim) ----------------
static cudaStream_t g_s2 = 0;
static cudaEvent_t  g_evFork = 0, g_evJoin = 0;

extern "C" void kernel_launch(void* const* d_in, const int* in_sizes, int n_in,
                              void* d_out, int out_size) {
    const float* emb  = (const float*)d_in[0];
    const int*   trip = (const int*)d_in[1];
    const float* apw  = (const float*)d_in[2];
    const float* apb  = (const float*)d_in[3];
    const float* abin = (const float*)d_in[4];
    const float* avec = (const float*)d_in[5];
    const float* agw  = (const float*)d_in[6];
    const float* agb  = (const float*)d_in[7];
    float* out = (float*)d_out;

    if (g_s2 == 0) {
        cudaStreamCreateWithFlags(&g_s2, cudaStreamNonBlocking);
        cudaEventCreateWithFlags(&g_evFork, cudaEventDisableTiming);
        cudaEventCreateWithFlags(&g_evJoin, cudaEventDisableTiming);
    }

    cudaEventRecord(g_evFork, 0);
    cudaStreamWaitEvent(g_s2, g_evFork, 0);

    K_zero   <<<(NUM_REL   + 255) / 256, 256, 0, g_s2>>>();
    K_hist   <<<(NUM_EDGES + 255) / 256, 256, 0, g_s2>>>(trip);
    K_scan1  <<<SCAN_B, 256, 0, g_s2>>>();
    K_scan2  <<<1, 128, 0, g_s2>>>();
    K_scan3  <<<SCAN_B, 256, 0, g_s2>>>();
    K_scatter<<<(NUM_EDGES + 255) / 256, 256, 0, g_s2>>>(trip);
    cudaEventRecord(g_evJoin, g_s2);

    K_pre <<<(3 * DIM * DIM + 255) / 256, 256>>>(apw, agw);
    K_gemm<<<dim3(NUM_REL / 32, 3), 256>>>(emb, apb, agb);

    cudaStreamWaitEvent(0, g_evJoin, 0);
    K_main<<<NUM_REL / 8, 256>>>(abin, avec, out);
}

// round 17
// speedup vs baseline: 1.1130x; 1.0177x over previous
#include <cuda_runtime.h>
#include <cuda_bf16.h>

#define NUM_REL   20000
#define NUM_EDGES 640000
#define DIM       128
#define NUM_HEAD  8
#define DIM_HID   16
#define NUM_BIN   10
#define NEG       0.2f
#define SCAN_B    79    // ceil(20000/256)

#define PACK2(u, lo, hi)  asm("mov.b64 %0, {%1, %2};" : "=l"(u) : "f"(lo), "f"(hi))
#define UNPACK2(lo, hi, u) asm("mov.b64 {%0, %1}, %2;" : "=f"(lo), "=f"(hi) : "l"(u))
#define FMA2(d, a, b, c)  asm("fma.rn.f32x2 %0, %1, %2, %3;" : "=l"(d) : "l"(a), "l"(b), "l"(c))

// ---------------- device scratch (static: no allocs allowed) ----------------
__device__ float g_P1[NUM_REL * DIM];
__device__ float g_PM[NUM_REL * 256];   // interleaved: [rel][0:128)=P2 row, [128:256)=M row
__device__ float g_Wt1[DIM * DIM];
__device__ float g_Wt2[DIM * DIM];
__device__ float g_Wt3[DIM * DIM];
__device__ int   g_cnt[NUM_REL];
__device__ int   g_off[NUM_REL + 1];
__device__ int   g_cur[NUM_REL];
__device__ int   g_sorted[NUM_EDGES];   // packed: tail | (bin << 20)
__device__ int   g_bsum[SCAN_B + 1];
__device__ int   g_ctr;                 // K_main work-stealing counter

// ---------------- weight transpose + counter reset ----------------
__global__ void K_pre(const float* __restrict__ attn_w, const float* __restrict__ aggr_w) {
    int id = blockIdx.x * blockDim.x + threadIdx.x;
    if (id == 0) g_ctr = 0;
    if (id >= 3 * DIM * DIM) return;
    int mtx = id / (DIM * DIM);
    int rem = id % (DIM * DIM);
    int j = rem / DIM, k = rem % DIM;
    if (mtx == 0)       g_Wt1[k * DIM + j] = attn_w[j * (2 * DIM) + k];
    else if (mtx == 1)  g_Wt2[k * DIM + j] = attn_w[j * (2 * DIM) + DIM + k];
    else                g_Wt3[k * DIM + j] = aggr_w[j * DIM + k];
}

__global__ void K_zero() {
    int i = blockIdx.x * blockDim.x + threadIdx.x;
    if (i < NUM_REL) g_cnt[i] = 0;
}

__global__ void K_hist(const int* __restrict__ trip) {
    int e = blockIdx.x * blockDim.x + threadIdx.x;
    if (e < NUM_EDGES) atomicAdd(&g_cnt[trip[e * 3]], 1);
}

// ---------------- 3-phase parallel scan ----------------
__global__ void K_scan1() {
    __shared__ int sh[256];
    int tid = threadIdx.x;
    int i = blockIdx.x * 256 + tid;
    int v = (i < NUM_REL) ? g_cnt[i] : 0;
    sh[tid] = v;
    __syncthreads();
#pragma unroll
    for (int off = 1; off < 256; off <<= 1) {
        int t = (tid >= off) ? sh[tid - off] : 0;
        __syncthreads();
        sh[tid] += t;
        __syncthreads();
    }
    if (i < NUM_REL) g_off[i] = sh[tid] - v;
    if (tid == 255) g_bsum[blockIdx.x] = sh[255];
}

__global__ void K_scan2() {
    __shared__ int sh[128];
    int tid = threadIdx.x;
    int v = (tid < SCAN_B) ? g_bsum[tid] : 0;
    sh[tid] = v;
    __syncthreads();
#pragma unroll
    for (int off = 1; off < 128; off <<= 1) {
        int t = (tid >= off) ? sh[tid - off] : 0;
        __syncthreads();
        sh[tid] += t;
        __syncthreads();
    }
    if (tid < SCAN_B) g_bsum[tid] = sh[tid] - v;
    if (tid == 127) g_off[NUM_REL] = sh[127];
}

__global__ void K_scan3() {
    int i = blockIdx.x * 256 + threadIdx.x;
    if (i < NUM_REL) {
        int o = g_off[i] + g_bsum[blockIdx.x];
        g_off[i] = o;
        g_cur[i] = o;
    }
}

__global__ void K_scatter(const int* __restrict__ trip) {
    int e = blockIdx.x * blockDim.x + threadIdx.x;
    if (e < NUM_EDGES) {
        int h    = trip[e * 3];
        int tail = trip[e * 3 + 1];
        int bin  = trip[e * 3 + 2];
        int pos = atomicAdd(&g_cur[h], 1);
        g_sorted[pos] = tail | (bin << 20);
    }
}

// ------- 20000x128x128 SGEMM (R15 verbatim) -------
#define ET_STRIDE 36
__global__ void __launch_bounds__(256) K_gemm(const float* __restrict__ emb,
                                              const float* __restrict__ apb,
                                              const float* __restrict__ agb) {
    int which = blockIdx.y;
    const float* __restrict__ Wt = (which == 0) ? g_Wt1 : (which == 1) ? g_Wt2 : g_Wt3;
    float*       __restrict__ op = (which == 0) ? g_P1  : g_PM;
    int ostride = (which == 0) ? 128 : 256;
    int ooff    = (which == 2) ? 128 : 0;
    const float* bias = (which == 0) ? apb : (which == 1) ? (const float*)0 : agb;

    __shared__ float eT[128 * ET_STRIDE];
    __shared__ float WtS[32 * 132];

    int tid = threadIdx.x;
    int rbase = blockIdx.x * 32;

    for (int idx = tid; idx < 32 * 128; idx += 256) {
        int rr = idx >> 7;
        int kk = idx & 127;
        eT[kk * ET_STRIDE + rr] = emb[(size_t)(rbase + rr) * DIM + kk];
    }

    int jt = tid & 31, j0 = jt * 4;
    int rt = tid >> 5, r0 = rt * 4;

    unsigned long long acc01[4], acc23[4];
#pragma unroll
    for (int a = 0; a < 4; a++) { acc01[a] = 0ull; acc23[a] = 0ull; }

    for (int kc = 0; kc < 4; kc++) {
        __syncthreads();
#pragma unroll
        for (int i = 0; i < 4; i++) {
            int v = tid + i * 256;
            int kl = v >> 5, jq = v & 31;
            *(float4*)&WtS[kl * 132 + jq * 4] = ((const float4*)Wt)[kc * 1024 + v];
        }
        __syncthreads();
#pragma unroll
        for (int kk = 0; kk < 32; kk++) {
            int k = kc * 32 + kk;
            float4 wv = *(float4*)&WtS[kk * 132 + j0];
            float4 ev = *(float4*)&eT[k * ET_STRIDE + r0];
            unsigned long long w01, w23;
            PACK2(w01, wv.x, wv.y);
            PACK2(w23, wv.z, wv.w);
            unsigned long long ee;
            PACK2(ee, ev.x, ev.x);
            FMA2(acc01[0], ee, w01, acc01[0]);
            FMA2(acc23[0], ee, w23, acc23[0]);
            PACK2(ee, ev.y, ev.y);
            FMA2(acc01[1], ee, w01, acc01[1]);
            FMA2(acc23[1], ee, w23, acc23[1]);
            PACK2(ee, ev.z, ev.z);
            FMA2(acc01[2], ee, w01, acc01[2]);
            FMA2(acc23[2], ee, w23, acc23[2]);
            PACK2(ee, ev.w, ev.w);
            FMA2(acc01[3], ee, w01, acc01[3]);
            FMA2(acc23[3], ee, w23, acc23[3]);
        }
    }

    float4 bv = make_float4(0.f, 0.f, 0.f, 0.f);
    if (bias) bv = *(const float4*)(bias + j0);
#pragma unroll
    for (int a = 0; a < 4; a++) {
        float4 o;
        UNPACK2(o.x, o.y, acc01[a]);
        UNPACK2(o.z, o.w, acc23[a]);
        o.x += bv.x; o.y += bv.y; o.z += bv.z; o.w += bv.w;
        *(float4*)&op[(size_t)(rbase + r0 + a) * ostride + ooff + j0] = o;
    }
}

// ------- persistent warps + dynamic relation stealing; R15 inner body verbatim -------
__global__ void __launch_bounds__(256) K_main(const float* __restrict__ attn_bin,
                                              const float* __restrict__ attn_vec,
                                              float* __restrict__ out) {
    __shared__ float binS[NUM_BIN * NUM_HEAD];

    int tid = threadIdx.x;
    int lane = tid & 31, h = lane >> 2;

    if (tid < NUM_BIN * NUM_HEAD) {
        float b = attn_bin[tid];
        binS[tid] = (b >= 0.f) ? b : NEG * b;
    }
    __syncthreads();

    float4 v = *(const float4*)(attn_vec + lane * 4);

    while (true) {
        int r = 0;
        if (lane == 0) r = atomicAdd(&g_ctr, 1);
        r = __shfl_sync(0xffffffffu, r, 0);
        if (r >= NUM_REL) break;

        int start = g_off[r];
        int cnt = g_off[r + 1] - start;

        if (cnt == 0) {
            *(float4*)(out + (size_t)r * 128 + lane * 4) = make_float4(0.f, 0.f, 0.f, 0.f);
            continue;
        }

        float4 p1 = *(const float4*)(g_P1 + (size_t)r * 128 + lane * 4);

        float m = -3.0e38f, s = 0.f;
        float4 acc = make_float4(0.f, 0.f, 0.f, 0.f);

        for (int base = 0; base < cnt; base += 32) {
            int rem = cnt - base;
            int n = (rem < 32) ? rem : 32;
            int myval = (lane < rem) ? g_sorted[start + base + lane] : 0;
#pragma unroll 4
            for (int i = 0; i < n; i++) {
                int val  = __shfl_sync(0xffffffffu, myval, i);
                int tail = val & 0xFFFFF;
                int bin  = val >> 20;
                const float* pm = g_PM + (size_t)tail * 256 + lane * 4;
                float4 p2 = *(const float4*)pm;
                float4 mv = *(const float4*)(pm + 128);
                float x0 = p1.x + p2.x; x0 = (x0 >= 0.f) ? x0 : NEG * x0;
                float x1 = p1.y + p2.y; x1 = (x1 >= 0.f) ? x1 : NEG * x1;
                float x2 = p1.z + p2.z; x2 = (x2 >= 0.f) ? x2 : NEG * x2;
                float x3 = p1.w + p2.w; x3 = (x3 >= 0.f) ? x3 : NEG * x3;
                float part = x0 * v.x + x1 * v.y + x2 * v.z + x3 * v.w;
                part += __shfl_xor_sync(0xffffffffu, part, 1);
                part += __shfl_xor_sync(0xffffffffu, part, 2);
                float score = part + binS[bin * 8 + h];
                if (score > m) {
                    float c = __expf(m - score);
                    s *= c;
                    acc.x *= c; acc.y *= c; acc.z *= c; acc.w *= c;
                    m = score;
                }
                float wt = __expf(score - m);
                s += wt;
                acc.x = fmaf(wt, mv.x, acc.x);
                acc.y = fmaf(wt, mv.y, acc.y);
                acc.z = fmaf(wt, mv.z, acc.z);
                acc.w = fmaf(wt, mv.w, acc.w);
            }
        }

        float inv = 1.f / (s + 1e-16f);
        float4 o;
        o.x = acc.x * inv; o.y = acc.y * inv; o.z = acc.z * inv; o.w = acc.w * inv;
        *(float4*)(out + (size_t)r * 128 + lane * 4) = o;
    }
}

// ---------------- launch: sort chain forked onto a second stream ----------------
static cudaStream_t g_s2 = 0;
static cudaEvent_t  g_evFork = 0, g_evJoin = 0;

extern "C" void kernel_launch(void* const* d_in, const int* in_sizes, int n_in,
                              void* d_out, int out_size) {
    const float* emb  = (const float*)d_in[0];
    const int*   trip = (const int*)d_in[1];
    const float* apw  = (const float*)d_in[2];
    const float* apb  = (const float*)d_in[3];
    const float* abin = (const float*)d_in[4];
    const float* avec = (const float*)d_in[5];
    const float* agw  = (const float*)d_in[6];
    const float* agb  = (const float*)d_in[7];
    float* out = (float*)d_out;

    if (g_s2 == 0) {
        cudaStreamCreateWithFlags(&g_s2, cudaStreamNonBlocking);
        cudaEventCreateWithFlags(&g_evFork, cudaEventDisableTiming);
        cudaEventCreateWithFlags(&g_evJoin, cudaEventDisableTiming);
    }

    cudaEventRecord(g_evFork, 0);
    cudaStreamWaitEvent(g_s2, g_evFork, 0);

    K_zero   <<<(NUM_REL   + 255) / 256, 256, 0, g_s2>>>();
    K_hist   <<<(NUM_EDGES + 255) / 256, 256, 0, g_s2>>>(trip);
    K_scan1  <<<SCAN_B, 256, 0, g_s2>>>();
    K_scan2  <<<1, 128, 0, g_s2>>>();
    K_scan3  <<<SCAN_B, 256, 0, g_s2>>>();
    K_scatter<<<(NUM_EDGES + 255) / 256, 256, 0, g_s2>>>(trip);
    cudaEventRecord(g_evJoin, g_s2);

    K_pre <<<(3 * DIM * DIM + 255) / 256, 256>>>(apw, agw);
    K_gemm<<<dim3(NUM_REL / 32, 3), 256>>>(emb, apb, agb);

    cudaStreamWaitEvent(0, g_evJoin, 0);
    K_main<<<4 * 148, 256>>>(abin, avec, out);   // persistent: ~4 blocks/SM, warps steal relations
}